// round 14
// baseline (speedup 1.0000x reference)
#include <cuda_runtime.h>
#include <math.h>

#define NSLOPE 0.2f
#define NN 1024
#define F 128

__device__ float g_XT[NN * F];   // feature-major activations [f][n]
__device__ float g_HT[NN * F];   // feature-major conv features [f][n]
__device__ float g_H[NN * F];    // row-major (final conv only)
__device__ float g_asf[NN];
__device__ float g_adf[NN];

__device__ __forceinline__ float lrelu(float x) { return x > 0.f ? x : NSLOPE * x; }

// order-preserving float->uint encode
__device__ __forceinline__ unsigned fenc(float f) {
    unsigned u = __float_as_uint(f);
    return (u & 0x80000000u) ? ~u : (u | 0x80000000u);
}

// ---------------------------------------------------------------------------
// GEMM. grid 512: (row-block 0..255) x (col-half 0..1); block 128 threads.
// 4 rows x 64 cols per block, 2 rows/thread (2048 warps chip-wide).
// W transposed in smem (pad 129).
// MODE 0: read desc1|desc2 rows, write HT; also zero asf/adf for MODE 2.
// MODE 1: read XT, write HT.
// MODE 2: read XT, write H (row-major) AND accumulate final-layer logits
//         asf[n]=H[n].a_s, adf[n]=H[n].a_d via lane-reduced atomicAdd.
template <int MODE>
__global__ void gemmT(const float* __restrict__ XT, const float* __restrict__ d1,
                      const float* __restrict__ d2, const float* __restrict__ W,
                      float* __restrict__ OUT, const float* __restrict__ a_s,
                      const float* __restrict__ a_d, float* __restrict__ asf,
                      float* __restrict__ adf) {
    __shared__ float Wt[64 * 129];
    __shared__ __align__(16) float xs[4][128];
    int tid = threadIdx.x;
    int bx = blockIdx.x;
    int cs = (bx & 1) * 64;
    int n0 = (bx >> 1) * 4;
    int c = tid & 63;
    int rh = tid >> 6;  // 0/1

    if (MODE == 0 && bx == 0) {
        // zero the final-layer logit accumulators (before gemmT<2> atomics;
        // re-done every replay -> deterministic)
#pragma unroll
        for (int i = 0; i < 8; i++) {
            asf[tid + i * 128] = 0.f;
            adf[tid + i * 128] = 0.f;
        }
    }

    // W[k][cs..cs+63] transposed into Wt[c][k]
#pragma unroll
    for (int i = 0; i < 16; i++) {
        int f = tid + i * 128;
        int k = f >> 4, cq = f & 15;
        float4 w4 = *reinterpret_cast<const float4*>(W + k * F + cs + cq * 4);
        Wt[(cq * 4 + 0) * 129 + k] = w4.x;
        Wt[(cq * 4 + 1) * 129 + k] = w4.y;
        Wt[(cq * 4 + 2) * 129 + k] = w4.z;
        Wt[(cq * 4 + 3) * 129 + k] = w4.w;
    }
    // 4 rows of input into xs[r][k]
    if (MODE == 0) {
        int r = tid >> 5, cq = tid & 31;
        int n = n0 + r;
        float4 x4 = (n < 512) ? reinterpret_cast<const float4*>(d1)[n * 32 + cq]
                              : reinterpret_cast<const float4*>(d2)[(n - 512) * 32 + cq];
        *reinterpret_cast<float4*>(&xs[r][cq * 4]) = x4;
    } else {
        const float4* XT4 = reinterpret_cast<const float4*>(XT);
        // one float4 (4 consecutive nodes n0..n0+3) per feature k = tid
        float4 x4 = XT4[tid * 256 + (bx >> 1)];
        xs[0][tid] = x4.x;
        xs[1][tid] = x4.y;
        xs[2][tid] = x4.z;
        xs[3][tid] = x4.w;
    }
    __syncthreads();

    float a0 = 0.f, a1 = 0.f;
#pragma unroll 4
    for (int kq = 0; kq < 32; kq++) {
        float w0 = Wt[c * 129 + kq * 4 + 0];
        float w1 = Wt[c * 129 + kq * 4 + 1];
        float w2 = Wt[c * 129 + kq * 4 + 2];
        float w3 = Wt[c * 129 + kq * 4 + 3];
        float4 x0 = *reinterpret_cast<const float4*>(&xs[rh * 2 + 0][kq * 4]);
        float4 x1 = *reinterpret_cast<const float4*>(&xs[rh * 2 + 1][kq * 4]);
        a0 = fmaf(x0.x, w0, fmaf(x0.y, w1, fmaf(x0.z, w2, fmaf(x0.w, w3, a0))));
        a1 = fmaf(x1.x, w0, fmaf(x1.y, w1, fmaf(x1.z, w2, fmaf(x1.w, w3, a1))));
    }
    if (MODE == 2) {
        float sca = a_s[cs + c];
        float scd = a_d[cs + c];
        int lane = tid & 31;
        float av[2] = {a0, a1};
#pragma unroll
        for (int r = 0; r < 2; r++) {
            int n = n0 + rh * 2 + r;
            OUT[n * F + cs + c] = av[r];
            // fused dots: reduce av[r]*a over the 32 lanes (consecutive cols)
            float s1 = av[r] * sca;
            float s2 = av[r] * scd;
#pragma unroll
            for (int o = 16; o; o >>= 1) {
                s1 += __shfl_xor_sync(0xffffffffu, s1, o);
                s2 += __shfl_xor_sync(0xffffffffu, s2, o);
            }
            if (lane == 0) {
                atomicAdd(&asf[n], s1);
                atomicAdd(&adf[n], s2);
            }
        }
    } else {
        float* p = OUT + (cs + c) * NN + n0 + rh * 2;
        *reinterpret_cast<float2*>(p) = make_float2(a0, a1);
    }
}

// ---------------------------------------------------------------------------
__device__ __forceinline__ float2 warp_incl_scan2(float2 v, int lane) {
#pragma unroll
    for (int d = 1; d < 32; d <<= 1) {
        float x = __shfl_up_sync(0xffffffffu, v.x, d);
        float y = __shfl_up_sync(0xffffffffu, v.y, d);
        if (lane >= d) { v.x += x; v.y += y; }
    }
    return v;
}
__device__ __forceinline__ float2 warp_incl_sufscan2(float2 v, int lane) {
#pragma unroll
    for (int d = 1; d < 32; d <<= 1) {
        float x = __shfl_down_sync(0xffffffffu, v.x, d);
        float y = __shfl_down_sync(0xffffffffu, v.y, d);
        if (lane + d < 32) { v.x += x; v.y += y; }
    }
    return v;
}

// ---------------------------------------------------------------------------
// GAT attention (128 heads, C=1): ONE block per head, 1024 threads = both
// dst-groups (dg = tid>>9) in lockstep on disjoint smem halves -> grid 128
// = a single wave on 148 SMs (removes the 1.73-wave quantization).
// Packed-key bitonic sort (order-preserving encode | 9-bit src index),
// exact keys/values regathered by index for the branch-sum scans.
template <bool CROSS>
__global__ void attnT(const float* __restrict__ HT, const float* __restrict__ a_src,
                      const float* __restrict__ a_dst, const float* __restrict__ bias,
                      float* __restrict__ XTo) {
    __shared__ unsigned sU[2][512];
    __shared__ float sK0[2][512];
    __shared__ float sV0[2][512];
    __shared__ __align__(16) float4 sSP[2][513];  // (suf1, suf1v, pre2, pre2v)
    __shared__ float2 wt1[2][16], wt2[2][16];

    int tid = threadIdx.x;      // 0..1023
    int dg = tid >> 9;          // dst group 0/1
    int t = tid & 511;          // element index within group
    int lane = tid & 31;
    int w = (tid >> 5) & 15;    // warp 0..15 within half
    int h = blockIdx.x;
    int sg = CROSS ? (1 - dg) : dg;

    float asrc = a_src[h], adst = a_dst[h], bh = bias[h];

    float sv = HT[h * NN + sg * 512 + t];
    float hd = HT[h * NN + dg * 512 + t];
    float kk = sv * asrc;
    sK0[dg][t] = kk;
    sV0[dg][t] = sv;
    unsigned u = (fenc(kk) & ~511u) | (unsigned)t;
    __syncthreads();

    // bitonic sort ascending on packed keys (both halves in lockstep)
    for (int K2 = 2; K2 <= 512; K2 <<= 1) {
        for (int J = K2 >> 1; J; J >>= 1) {
            bool keepSmall = (((t & K2) == 0) == ((t & J) == 0));
            unsigned uo;
            if (J >= 32) {
                __syncthreads();
                sU[dg][t] = u;
                __syncthreads();
                uo = sU[dg][t ^ J];
            } else {
                uo = __shfl_xor_sync(0xffffffffu, u, J);
            }
            u = keepSmall ? umin(u, uo) : umax(u, uo);
        }
    }

    __syncthreads();
    sU[dg][t] = u;
    __syncthreads();
    float M = sK0[dg][sU[dg][511] & 511u];

    // regather exact key/value of this thread's sorted element
    unsigned idx = u & 511u;
    float kx = sK0[dg][idx];
    float vx = sV0[dg][idx];

    float q1 = __expf(kx - M);
    float q2 = __expf(NSLOPE * (kx - M));
    float2 p1 = make_float2(q1, q1 * vx);
    float2 p2 = make_float2(q2, q2 * vx);

    // block scans in sorted order (element order == t, per half)
    float2 tincl = warp_incl_scan2(p2, lane);   // inclusive prefix of p2
    float2 texcl;
    texcl.x = __shfl_up_sync(0xffffffffu, tincl.x, 1);
    texcl.y = __shfl_up_sync(0xffffffffu, tincl.y, 1);
    if (lane == 0) texcl = make_float2(0.f, 0.f);
    if (lane == 31) wt2[dg][w] = tincl;

    float2 sincl = warp_incl_sufscan2(p1, lane);  // inclusive suffix of p1
    if (lane == 0) wt1[dg][w] = sincl;
    __syncthreads();

    float2 base2 = texcl, base1 = make_float2(0.f, 0.f);
#pragma unroll
    for (int ww = 0; ww < 16; ww++) {
        if (ww < w) { base2.x += wt2[dg][ww].x; base2.y += wt2[dg][ww].y; }
        if (ww > w) { base1.x += wt1[dg][ww].x; base1.y += wt1[dg][ww].y; }
    }
    sSP[dg][t] = make_float4(base1.x + sincl.x, base1.y + sincl.y, base2.x, base2.y);
    // total prefix = warp offsets + own element p2 (base2 already holds texcl)
    if (t == 511)
        sSP[dg][512] = make_float4(0.f, 0.f, base2.x + p2.x, base2.y + p2.y);
    __syncthreads();

    // per-dst: binary search rank of threshold -ad (encoded domain)
    float adv = hd * adst;
    unsigned ue = fenc(-adv);
    int pos = 0;
#pragma unroll
    for (int half = 256; half >= 1; half >>= 1)
        if (sU[dg][pos + half - 1] <= ue) pos += half;
    if (sU[dg][pos] <= ue) pos++;

    float4 Sv = sSP[dg][pos];
    float T = M + adv;
    float tmax = T, ts = 0.f;
    if (CROSS) {
        ts = hd * asrc + adv;  // self-loop score
        tmax = fmaxf(tmax, ts);
    }
    float C = lrelu(tmax);
    float f1 = __expf(T - C);
    float f2 = __expf(NSLOPE * T - C);
    float num = f1 * Sv.y + f2 * Sv.w;
    float den = f1 * Sv.x + f2 * Sv.z;
    if (CROSS) {
        float ws = __expf(lrelu(ts) - C);
        num = fmaf(ws, hd, num);
        den += ws;
    }
    float o = num / (den + 1e-16f) + bh;
    o = o > 0.f ? o : expm1f(o);  // ELU
    XTo[h * NN + dg * 512 + t] = o;
}

// ---------------------------------------------------------------------------
// final cross-attention: 8 dsts/block, 256 threads (128 cols x 2 s-halves)
__global__ void final_attn(const float* __restrict__ H, const float* __restrict__ asf,
                           const float* __restrict__ adf, const float* __restrict__ bias,
                           float* __restrict__ out) {
    int d0 = blockIdx.x * 8;
    int dg = d0 >> 9;
    int sg = 1 - dg;
    int tid = threadIdx.x;
    int col = tid & 127, sh = tid >> 7;
    int w = tid >> 5, lane = tid & 31;

    __shared__ float sAsf[512];
    __shared__ float4 swq[512][2];
    __shared__ float sAdf[8], sM[8], sSelf[8], sDen[8];
    __shared__ float pr[8][128];
    __shared__ float dred[8][256];
    __shared__ float red[8];

    float mloc = -1e30f;
    for (int s = tid; s < 512; s += 256) {
        float v = asf[sg * 512 + s];
        sAsf[s] = v;
        mloc = fmaxf(mloc, v);
    }
#pragma unroll
    for (int o = 16; o; o >>= 1) mloc = fmaxf(mloc, __shfl_xor_sync(0xffffffffu, mloc, o));
    if (lane == 0) red[w] = mloc;
    __syncthreads();
    float maxasf = red[0];
#pragma unroll
    for (int ww = 1; ww < 8; ww++) maxasf = fmaxf(maxasf, red[ww]);

    if (tid < 8) {
        int dn = d0 + tid;
        float ad = adf[dn];
        float ts = asf[dn] + ad;
        float tmax = fmaxf(maxasf + ad, ts);
        float mm = lrelu(tmax);
        sAdf[tid] = ad;
        sM[tid] = mm;
        sSelf[tid] = __expf(lrelu(ts) - mm);
    }
    __syncthreads();

    float dl[8] = {0, 0, 0, 0, 0, 0, 0, 0};
    for (int s = tid; s < 512; s += 256) {
        float a = sAsf[s];
        float wv[8];
#pragma unroll
        for (int d = 0; d < 8; d++) {
            wv[d] = __expf(lrelu(a + sAdf[d]) - sM[d]);
            dl[d] += wv[d];
        }
        swq[s][0] = make_float4(wv[0], wv[1], wv[2], wv[3]);
        swq[s][1] = make_float4(wv[4], wv[5], wv[6], wv[7]);
    }
#pragma unroll
    for (int d = 0; d < 8; d++) dred[d][tid] = dl[d];
    __syncthreads();
    {
        float x = dred[w][lane] + dred[w][lane + 32] + dred[w][lane + 64] + dred[w][lane + 96] +
                  dred[w][lane + 128] + dred[w][lane + 160] + dred[w][lane + 192] + dred[w][lane + 224];
#pragma unroll
        for (int o = 16; o; o >>= 1) x += __shfl_xor_sync(0xffffffffu, x, o);
        if (lane == 0) sDen[w] = x;
    }
    __syncthreads();

    float acc[8] = {0, 0, 0, 0, 0, 0, 0, 0};
    const float* Hs = H + (sg * 512 + sh * 256) * F + col;
#pragma unroll 2
    for (int s = 0; s < 256; s++) {
        float hv = Hs[s * F];
        int ss = sh * 256 + s;
        float4 w0 = swq[ss][0];
        float4 w1 = swq[ss][1];
        acc[0] = fmaf(w0.x, hv, acc[0]);
        acc[1] = fmaf(w0.y, hv, acc[1]);
        acc[2] = fmaf(w0.z, hv, acc[2]);
        acc[3] = fmaf(w0.w, hv, acc[3]);
        acc[4] = fmaf(w1.x, hv, acc[4]);
        acc[5] = fmaf(w1.y, hv, acc[5]);
        acc[6] = fmaf(w1.z, hv, acc[6]);
        acc[7] = fmaf(w1.w, hv, acc[7]);
    }
    if (sh) {
#pragma unroll
        for (int d = 0; d < 8; d++) pr[d][col] = acc[d];
    }
    __syncthreads();
    if (!sh) {
        float bc = bias[col];
#pragma unroll
        for (int d = 0; d < 8; d++) {
            int dn = d0 + d;
            float Hdv = H[dn * F + col];
            float num = acc[d] + pr[d][col] + sSelf[d] * Hdv;
            out[dn * F + col] = num / (sDen[d] + sSelf[d] + 1e-16f) + bc;
        }
    }
}

// ---------------------------------------------------------------------------
extern "C" void kernel_launch(void* const* d_in, const int* in_sizes, int n_in,
                              void* d_out, int out_size) {
    const float* desc1 = (const float*)d_in[0];
    const float* desc2 = (const float*)d_in[1];
    const float* W1 = (const float*)d_in[2];
    const float* as1 = (const float*)d_in[3];
    const float* ad1 = (const float*)d_in[4];
    const float* b1 = (const float*)d_in[5];
    const float* W2 = (const float*)d_in[6];
    const float* as2 = (const float*)d_in[7];
    const float* ad2 = (const float*)d_in[8];
    const float* b2 = (const float*)d_in[9];
    float* out = (float*)d_out;

    float *XT, *HT, *H, *asf, *adf;
    cudaGetSymbolAddress((void**)&XT, g_XT);
    cudaGetSymbolAddress((void**)&HT, g_HT);
    cudaGetSymbolAddress((void**)&H, g_H);
    cudaGetSymbolAddress((void**)&asf, g_asf);
    cudaGetSymbolAddress((void**)&adf, g_adf);

    const float* np = nullptr;
    // conv1: inside (concat fused into gemm; also zeroes asf/adf for later)
    gemmT<0><<<512, 128>>>(np, desc1, desc2, W1, HT, np, np, asf, adf);
    attnT<false><<<128, 1024>>>(HT, as1, ad1, b1, XT);
    // conv2: cross
    gemmT<1><<<512, 128>>>(XT, np, np, W1, HT, np, np, asf, adf);
    attnT<true><<<128, 1024>>>(HT, as1, ad1, b1, XT);
    // conv3: inside
    gemmT<1><<<512, 128>>>(XT, np, np, W1, HT, np, np, asf, adf);
    attnT<false><<<128, 1024>>>(HT, as1, ad1, b1, XT);
    // conv4: cross
    gemmT<1><<<512, 128>>>(XT, np, np, W1, HT, np, np, asf, adf);
    attnT<true><<<128, 1024>>>(HT, as1, ad1, b1, XT);
    // final conv: cross, heads=1, out_ch=128 (row-major H + fused dots)
    gemmT<2><<<512, 128>>>(XT, np, np, W2, H, as2, ad2, asf, adf);
    final_attn<<<128, 256>>>(H, asf, adf, b2, out);
}

// round 15
// speedup vs baseline: 1.0898x; 1.0898x over previous
#include <cuda_runtime.h>
#include <math.h>

#define NSLOPE 0.2f
#define NN 1024
#define F 128

__device__ float g_XT[NN * F];   // feature-major activations [f][n]
__device__ float g_HT[NN * F];   // feature-major conv features [f][n]
__device__ float g_H[NN * F];    // row-major (final conv only)
__device__ float g_asf[NN];
__device__ float g_adf[NN];

__device__ __forceinline__ float lrelu(float x) { return x > 0.f ? x : NSLOPE * x; }

// order-preserving float->uint encode
__device__ __forceinline__ unsigned fenc(float f) {
    unsigned u = __float_as_uint(f);
    return (u & 0x80000000u) ? ~u : (u | 0x80000000u);
}

// ---------------------------------------------------------------------------
// GEMM v3 ("warp-rich"): grid 128 (8 nodes/block), block 512 = 4 k-groups
// x 128 cols -> 2048 warps chip-wide (2x R13). W is read DIRECTLY from L2,
// coalesced (lane = col -> 128B per warp per k); no smem W staging. Each
// thread: 8 row-accs over its 32-k slice (256 FMA). k-partials combined via
// smem in fixed order (deterministic).
// MODE 0: read desc1|desc2 rows (row-major), write HT.
// MODE 1: read XT (feature-major), write HT.
// MODE 2: read XT, write H (row-major).
template <int MODE>
__global__ void gemmW(const float* __restrict__ XT, const float* __restrict__ d1,
                      const float* __restrict__ d2, const float* __restrict__ W,
                      float* __restrict__ OUT) {
    __shared__ __align__(16) float xs[8][128];
    __shared__ float pr[3][8][128];  // partials from ks = 1..3
    int tid = threadIdx.x;
    int c = tid & 127;
    int ks = tid >> 7;  // 0..3
    int n0 = blockIdx.x * 8;

    // stage the 8 input rows (all 128 features) into xs[r][k]
    if (MODE == 0) {
#pragma unroll
        for (int i = 0; i < 2; i++) {
            int u = tid + i * 512;  // 0..1023
            int r = u >> 7, f = u & 127;
            int n = n0 + r;
            xs[r][f] = (n < 512) ? d1[n * F + f] : d2[(n - 512) * F + f];
        }
    } else {
        if (tid < 256) {
            int k = tid >> 1, q = tid & 1;  // feature k, node-quad q (4 nodes)
            float4 x4 = reinterpret_cast<const float4*>(XT)[k * 256 + (n0 >> 2) + q];
            xs[q * 4 + 0][k] = x4.x;
            xs[q * 4 + 1][k] = x4.y;
            xs[q * 4 + 2][k] = x4.z;
            xs[q * 4 + 3][k] = x4.w;
        }
    }
    __syncthreads();

    // inner: this ks-group covers k in [ks*32, ks*32+32)
    float acc[8] = {0, 0, 0, 0, 0, 0, 0, 0};
    const float* Wp = W + (ks * 32) * F + c;
#pragma unroll
    for (int kq = 0; kq < 8; kq++) {
        float w0 = Wp[(kq * 4 + 0) * F];
        float w1 = Wp[(kq * 4 + 1) * F];
        float w2 = Wp[(kq * 4 + 2) * F];
        float w3 = Wp[(kq * 4 + 3) * F];
        int k4 = ks * 32 + kq * 4;
#pragma unroll
        for (int r = 0; r < 8; r++) {
            float4 x = *reinterpret_cast<const float4*>(&xs[r][k4]);
            acc[r] = fmaf(x.x, w0, fmaf(x.y, w1, fmaf(x.z, w2, fmaf(x.w, w3, acc[r]))));
        }
    }

    // combine the 4 k-partials (fixed order -> deterministic)
    if (ks) {
#pragma unroll
        for (int r = 0; r < 8; r++) pr[ks - 1][r][c] = acc[r];
    }
    __syncthreads();
    if (!ks) {
        float o[8];
#pragma unroll
        for (int r = 0; r < 8; r++)
            o[r] = acc[r] + pr[0][r][c] + pr[1][r][c] + pr[2][r][c];
        if (MODE == 2) {
#pragma unroll
            for (int r = 0; r < 8; r++) OUT[(n0 + r) * F + c] = o[r];
        } else {
            // HT: 8 consecutive nodes for column c
            float* p = OUT + c * NN + n0;
            *reinterpret_cast<float4*>(p) = make_float4(o[0], o[1], o[2], o[3]);
            *reinterpret_cast<float4*>(p + 4) = make_float4(o[4], o[5], o[6], o[7]);
        }
    }
}

// ---------------------------------------------------------------------------
__device__ __forceinline__ float2 warp_incl_scan2(float2 v, int lane) {
#pragma unroll
    for (int d = 1; d < 32; d <<= 1) {
        float x = __shfl_up_sync(0xffffffffu, v.x, d);
        float y = __shfl_up_sync(0xffffffffu, v.y, d);
        if (lane >= d) { v.x += x; v.y += y; }
    }
    return v;
}
__device__ __forceinline__ float2 warp_incl_sufscan2(float2 v, int lane) {
#pragma unroll
    for (int d = 1; d < 32; d <<= 1) {
        float x = __shfl_down_sync(0xffffffffu, v.x, d);
        float y = __shfl_down_sync(0xffffffffu, v.y, d);
        if (lane + d < 32) { v.x += x; v.y += y; }
    }
    return v;
}

// ---------------------------------------------------------------------------
// GAT attention (128 heads, C=1), 1 head/block, grid (128, 2), 512 threads,
// 1 element/thread. Packed-key bitonic sort (order-preserving encode | 9-bit
// src index) -> one u32 min/max per exchange; exact keys/values regathered
// by index for the branch-sum scans.  [R13-proven: 8.3us, rel 7.2e-6]
template <bool CROSS>
__global__ void attnT(const float* __restrict__ HT, const float* __restrict__ a_src,
                      const float* __restrict__ a_dst, const float* __restrict__ bias,
                      float* __restrict__ XTo) {
    __shared__ unsigned sU[512];
    __shared__ float sK0[512];
    __shared__ float sV0[512];
    __shared__ __align__(16) float4 sSP[513];  // (suf1, suf1v, pre2, pre2v)
    __shared__ float2 wt1[16], wt2[16];

    int t = threadIdx.x;        // 0..511 = element index
    int lane = t & 31;
    int w = t >> 5;             // warp 0..15
    int h = blockIdx.x;
    int dg = blockIdx.y;
    int sg = CROSS ? (1 - dg) : dg;

    float asrc = a_src[h], adst = a_dst[h], bh = bias[h];

    float sv = HT[h * NN + sg * 512 + t];
    float hd = HT[h * NN + dg * 512 + t];
    float kk = sv * asrc;
    sK0[t] = kk;
    sV0[t] = sv;
    unsigned u = (fenc(kk) & ~511u) | (unsigned)t;
    __syncthreads();

    // bitonic sort ascending on packed keys
    for (int K2 = 2; K2 <= 512; K2 <<= 1) {
        for (int J = K2 >> 1; J; J >>= 1) {
            bool keepSmall = (((t & K2) == 0) == ((t & J) == 0));
            unsigned uo;
            if (J >= 32) {
                __syncthreads();
                sU[t] = u;
                __syncthreads();
                uo = sU[t ^ J];
            } else {
                uo = __shfl_xor_sync(0xffffffffu, u, J);
            }
            u = keepSmall ? umin(u, uo) : umax(u, uo);
        }
    }

    __syncthreads();
    sU[t] = u;
    __syncthreads();
    float M = sK0[sU[511] & 511u];

    // regather exact key/value of this thread's sorted element
    unsigned idx = u & 511u;
    float kx = sK0[idx];
    float vx = sV0[idx];

    float q1 = __expf(kx - M);
    float q2 = __expf(NSLOPE * (kx - M));
    float2 p1 = make_float2(q1, q1 * vx);
    float2 p2 = make_float2(q2, q2 * vx);

    // block scans in sorted order (element order == t)
    float2 tincl = warp_incl_scan2(p2, lane);   // inclusive prefix of p2
    float2 texcl;
    texcl.x = __shfl_up_sync(0xffffffffu, tincl.x, 1);
    texcl.y = __shfl_up_sync(0xffffffffu, tincl.y, 1);
    if (lane == 0) texcl = make_float2(0.f, 0.f);
    if (lane == 31) wt2[w] = tincl;

    float2 sincl = warp_incl_sufscan2(p1, lane);  // inclusive suffix of p1
    if (lane == 0) wt1[w] = sincl;
    __syncthreads();

    float2 base2 = texcl, base1 = make_float2(0.f, 0.f);
#pragma unroll
    for (int ww = 0; ww < 16; ww++) {
        if (ww < w) { base2.x += wt2[ww].x; base2.y += wt2[ww].y; }
        if (ww > w) { base1.x += wt1[ww].x; base1.y += wt1[ww].y; }
    }
    sSP[t] = make_float4(base1.x + sincl.x, base1.y + sincl.y, base2.x, base2.y);
    // total prefix = warp offsets + own element p2 (base2 already holds texcl)
    if (t == 511)
        sSP[512] = make_float4(0.f, 0.f, base2.x + p2.x, base2.y + p2.y);
    __syncthreads();

    // per-dst: binary search rank of threshold -ad (encoded domain)
    float adv = hd * adst;
    unsigned ue = fenc(-adv);
    int pos = 0;
#pragma unroll
    for (int half = 256; half >= 1; half >>= 1)
        if (sU[pos + half - 1] <= ue) pos += half;
    if (sU[pos] <= ue) pos++;

    float4 Sv = sSP[pos];
    float T = M + adv;
    float tmax = T, ts = 0.f;
    if (CROSS) {
        ts = hd * asrc + adv;  // self-loop score
        tmax = fmaxf(tmax, ts);
    }
    float C = lrelu(tmax);
    float f1 = __expf(T - C);
    float f2 = __expf(NSLOPE * T - C);
    float num = f1 * Sv.y + f2 * Sv.w;
    float den = f1 * Sv.x + f2 * Sv.z;
    if (CROSS) {
        float ws = __expf(lrelu(ts) - C);
        num = fmaf(ws, hd, num);
        den += ws;
    }
    float o = num / (den + 1e-16f) + bh;
    o = o > 0.f ? o : expm1f(o);  // ELU
    XTo[h * NN + dg * 512 + t] = o;
}

// ---------------------------------------------------------------------------
__global__ void dots_kernel(const float* __restrict__ H, const float* __restrict__ a_s,
                            const float* __restrict__ a_d, float* __restrict__ asf,
                            float* __restrict__ adf) {
    int n = blockIdx.x * 8 + (threadIdx.x >> 5);
    int lane = threadIdx.x & 31;
    float4 hv = reinterpret_cast<const float4*>(H + n * F)[lane];
    float4 s4 = reinterpret_cast<const float4*>(a_s)[lane];
    float4 d4 = reinterpret_cast<const float4*>(a_d)[lane];
    float s1 = hv.x * s4.x + hv.y * s4.y + hv.z * s4.z + hv.w * s4.w;
    float s2 = hv.x * d4.x + hv.y * d4.y + hv.z * d4.z + hv.w * d4.w;
#pragma unroll
    for (int o = 16; o; o >>= 1) {
        s1 += __shfl_xor_sync(0xffffffffu, s1, o);
        s2 += __shfl_xor_sync(0xffffffffu, s2, o);
    }
    if (lane == 0) { asf[n] = s1; adf[n] = s2; }
}

// final cross-attention: 8 dsts/block, 256 threads (128 cols x 2 s-halves)
__global__ void final_attn(const float* __restrict__ H, const float* __restrict__ asf,
                           const float* __restrict__ adf, const float* __restrict__ bias,
                           float* __restrict__ out) {
    int d0 = blockIdx.x * 8;
    int dg = d0 >> 9;
    int sg = 1 - dg;
    int tid = threadIdx.x;
    int col = tid & 127, sh = tid >> 7;
    int w = tid >> 5, lane = tid & 31;

    __shared__ float sAsf[512];
    __shared__ float4 swq[512][2];
    __shared__ float sAdf[8], sM[8], sSelf[8], sDen[8];
    __shared__ float pr[8][128];
    __shared__ float dred[8][256];
    __shared__ float red[8];

    float mloc = -1e30f;
    for (int s = tid; s < 512; s += 256) {
        float v = asf[sg * 512 + s];
        sAsf[s] = v;
        mloc = fmaxf(mloc, v);
    }
#pragma unroll
    for (int o = 16; o; o >>= 1) mloc = fmaxf(mloc, __shfl_xor_sync(0xffffffffu, mloc, o));
    if (lane == 0) red[w] = mloc;
    __syncthreads();
    float maxasf = red[0];
#pragma unroll
    for (int ww = 1; ww < 8; ww++) maxasf = fmaxf(maxasf, red[ww]);

    if (tid < 8) {
        int dn = d0 + tid;
        float ad = adf[dn];
        float ts = asf[dn] + ad;
        float tmax = fmaxf(maxasf + ad, ts);
        float mm = lrelu(tmax);
        sAdf[tid] = ad;
        sM[tid] = mm;
        sSelf[tid] = __expf(lrelu(ts) - mm);
    }
    __syncthreads();

    float dl[8] = {0, 0, 0, 0, 0, 0, 0, 0};
    for (int s = tid; s < 512; s += 256) {
        float a = sAsf[s];
        float wv[8];
#pragma unroll
        for (int d = 0; d < 8; d++) {
            wv[d] = __expf(lrelu(a + sAdf[d]) - sM[d]);
            dl[d] += wv[d];
        }
        swq[s][0] = make_float4(wv[0], wv[1], wv[2], wv[3]);
        swq[s][1] = make_float4(wv[4], wv[5], wv[6], wv[7]);
    }
#pragma unroll
    for (int d = 0; d < 8; d++) dred[d][tid] = dl[d];
    __syncthreads();
    {
        float x = dred[w][lane] + dred[w][lane + 32] + dred[w][lane + 64] + dred[w][lane + 96] +
                  dred[w][lane + 128] + dred[w][lane + 160] + dred[w][lane + 192] + dred[w][lane + 224];
#pragma unroll
        for (int o = 16; o; o >>= 1) x += __shfl_xor_sync(0xffffffffu, x, o);
        if (lane == 0) sDen[w] = x;
    }
    __syncthreads();

    float acc[8] = {0, 0, 0, 0, 0, 0, 0, 0};
    const float* Hs = H + (sg * 512 + sh * 256) * F + col;
#pragma unroll 2
    for (int s = 0; s < 256; s++) {
        float hv = Hs[s * F];
        int ss = sh * 256 + s;
        float4 w0 = swq[ss][0];
        float4 w1 = swq[ss][1];
        acc[0] = fmaf(w0.x, hv, acc[0]);
        acc[1] = fmaf(w0.y, hv, acc[1]);
        acc[2] = fmaf(w0.z, hv, acc[2]);
        acc[3] = fmaf(w0.w, hv, acc[3]);
        acc[4] = fmaf(w1.x, hv, acc[4]);
        acc[5] = fmaf(w1.y, hv, acc[5]);
        acc[6] = fmaf(w1.z, hv, acc[6]);
        acc[7] = fmaf(w1.w, hv, acc[7]);
    }
    if (sh) {
#pragma unroll
        for (int d = 0; d < 8; d++) pr[d][col] = acc[d];
    }
    __syncthreads();
    if (!sh) {
        float bc = bias[col];
#pragma unroll
        for (int d = 0; d < 8; d++) {
            int dn = d0 + d;
            float Hdv = H[dn * F + col];
            float num = acc[d] + pr[d][col] + sSelf[d] * Hdv;
            out[dn * F + col] = num / (sDen[d] + sSelf[d] + 1e-16f) + bc;
        }
    }
}

// ---------------------------------------------------------------------------
extern "C" void kernel_launch(void* const* d_in, const int* in_sizes, int n_in,
                              void* d_out, int out_size) {
    const float* desc1 = (const float*)d_in[0];
    const float* desc2 = (const float*)d_in[1];
    const float* W1 = (const float*)d_in[2];
    const float* as1 = (const float*)d_in[3];
    const float* ad1 = (const float*)d_in[4];
    const float* b1 = (const float*)d_in[5];
    const float* W2 = (const float*)d_in[6];
    const float* as2 = (const float*)d_in[7];
    const float* ad2 = (const float*)d_in[8];
    const float* b2 = (const float*)d_in[9];
    float* out = (float*)d_out;

    float *XT, *HT, *H, *asf, *adf;
    cudaGetSymbolAddress((void**)&XT, g_XT);
    cudaGetSymbolAddress((void**)&HT, g_HT);
    cudaGetSymbolAddress((void**)&H, g_H);
    cudaGetSymbolAddress((void**)&asf, g_asf);
    cudaGetSymbolAddress((void**)&adf, g_adf);

    dim3 ag(128, 2);
    const float* np = nullptr;
    // conv1: inside (concat fused into gemm)
    gemmW<0><<<128, 512>>>(np, desc1, desc2, W1, HT);
    attnT<false><<<ag, 512>>>(HT, as1, ad1, b1, XT);
    // conv2: cross
    gemmW<1><<<128, 512>>>(XT, np, np, W1, HT);
    attnT<true><<<ag, 512>>>(HT, as1, ad1, b1, XT);
    // conv3: inside
    gemmW<1><<<128, 512>>>(XT, np, np, W1, HT);
    attnT<false><<<ag, 512>>>(HT, as1, ad1, b1, XT);
    // conv4: cross
    gemmW<1><<<128, 512>>>(XT, np, np, W1, HT);
    attnT<true><<<ag, 512>>>(HT, as1, ad1, b1, XT);
    // final conv: cross, heads=1, out_ch=128 (row-major H)
    gemmW<2><<<128, 512>>>(XT, np, np, W2, H);
    dots_kernel<<<128, 256>>>(H, as2, ad2, asf, adf);
    final_attn<<<128, 256>>>(H, asf, adf, b2, out);
}

// round 16
// speedup vs baseline: 1.0991x; 1.0086x over previous
#include <cuda_runtime.h>
#include <math.h>

#define NSLOPE 0.2f
#define NN 1024
#define F 128

__device__ float g_XT[NN * F];   // feature-major activations [f][n]
__device__ float g_HT[NN * F];   // feature-major conv features [f][n]
__device__ float g_H[NN * F];    // row-major (final conv only)
__device__ float g_asf[NN];
__device__ float g_adf[NN];

__device__ __forceinline__ float lrelu(float x) { return x > 0.f ? x : NSLOPE * x; }

// ---------------------------------------------------------------------------
// GEMM v3 (R15-proven): grid 128 (8 nodes/block), block 512 = 4 k-groups
// x 128 cols. W read directly from L2, coalesced. k-partials via smem.
template <int MODE>
__global__ void gemmW(const float* __restrict__ XT, const float* __restrict__ d1,
                      const float* __restrict__ d2, const float* __restrict__ W,
                      float* __restrict__ OUT) {
    __shared__ __align__(16) float xs[8][128];
    __shared__ float pr[3][8][128];  // partials from ks = 1..3
    int tid = threadIdx.x;
    int c = tid & 127;
    int ks = tid >> 7;  // 0..3
    int n0 = blockIdx.x * 8;

    if (MODE == 0) {
#pragma unroll
        for (int i = 0; i < 2; i++) {
            int u = tid + i * 512;  // 0..1023
            int r = u >> 7, f = u & 127;
            int n = n0 + r;
            xs[r][f] = (n < 512) ? d1[n * F + f] : d2[(n - 512) * F + f];
        }
    } else {
        if (tid < 256) {
            int k = tid >> 1, q = tid & 1;
            float4 x4 = reinterpret_cast<const float4*>(XT)[k * 256 + (n0 >> 2) + q];
            xs[q * 4 + 0][k] = x4.x;
            xs[q * 4 + 1][k] = x4.y;
            xs[q * 4 + 2][k] = x4.z;
            xs[q * 4 + 3][k] = x4.w;
        }
    }
    __syncthreads();

    float acc[8] = {0, 0, 0, 0, 0, 0, 0, 0};
    const float* Wp = W + (ks * 32) * F + c;
#pragma unroll
    for (int kq = 0; kq < 8; kq++) {
        float w0 = Wp[(kq * 4 + 0) * F];
        float w1 = Wp[(kq * 4 + 1) * F];
        float w2 = Wp[(kq * 4 + 2) * F];
        float w3 = Wp[(kq * 4 + 3) * F];
        int k4 = ks * 32 + kq * 4;
#pragma unroll
        for (int r = 0; r < 8; r++) {
            float4 x = *reinterpret_cast<const float4*>(&xs[r][k4]);
            acc[r] = fmaf(x.x, w0, fmaf(x.y, w1, fmaf(x.z, w2, fmaf(x.w, w3, acc[r]))));
        }
    }

    if (ks) {
#pragma unroll
        for (int r = 0; r < 8; r++) pr[ks - 1][r][c] = acc[r];
    }
    __syncthreads();
    if (!ks) {
        float o[8];
#pragma unroll
        for (int r = 0; r < 8; r++)
            o[r] = acc[r] + pr[0][r][c] + pr[1][r][c] + pr[2][r][c];
        if (MODE == 2) {
#pragma unroll
            for (int r = 0; r < 8; r++) OUT[(n0 + r) * F + c] = o[r];
        } else {
            float* p = OUT + c * NN + n0;
            *reinterpret_cast<float4*>(p) = make_float4(o[0], o[1], o[2], o[3]);
            *reinterpret_cast<float4*>(p + 4) = make_float4(o[4], o[5], o[6], o[7]);
        }
    }
}

// ---------------------------------------------------------------------------
__device__ __forceinline__ float2 warp_incl_scan2(float2 v, int lane) {
#pragma unroll
    for (int d = 1; d < 32; d <<= 1) {
        float x = __shfl_up_sync(0xffffffffu, v.x, d);
        float y = __shfl_up_sync(0xffffffffu, v.y, d);
        if (lane >= d) { v.x += x; v.y += y; }
    }
    return v;
}
__device__ __forceinline__ float2 warp_incl_sufscan2(float2 v, int lane) {
#pragma unroll
    for (int d = 1; d < 32; d <<= 1) {
        float x = __shfl_down_sync(0xffffffffu, v.x, d);
        float y = __shfl_down_sync(0xffffffffu, v.y, d);
        if (lane + d < 32) { v.x += x; v.y += y; }
    }
    return v;
}

// ---------------------------------------------------------------------------
// GAT attention v2: counting-sort/histogram ranking (no bitonic sort).
// Monotone binning: bin(k) = floor((k-m)*scale) preserves order, so bins
// below bin(thr) are entirely <= thr and bins above entirely > thr; only the
// boundary bin (avg ~1 element) needs exact per-element compares. Branch
// sums = float4 prefix/suffix scans over the counting-sorted order.
// grid (128, 2), 512 threads, 1 element/thread.
template <bool CROSS>
__global__ void attnH(const float* __restrict__ HT, const float* __restrict__ a_src,
                      const float* __restrict__ a_dst, const float* __restrict__ bias,
                      float* __restrict__ XTo) {
    __shared__ float sKsc[512];                 // scattered keys
    __shared__ __align__(16) float4 sP4[512];   // scattered (P1,P1v,P2,P2v)
    __shared__ __align__(16) float4 sSP[513];   // (suf1,suf1v,pre2,pre2v)
    __shared__ int cnt[512];
    __shared__ int bstart[513];
    __shared__ float redM[16], redm[16];
    __shared__ int wtot[16];
    __shared__ float2 wt1[16], wt2[16];

    int t = threadIdx.x;        // 0..511 = element index
    int lane = t & 31;
    int w = t >> 5;
    int h = blockIdx.x;
    int dg = blockIdx.y;
    int sg = CROSS ? (1 - dg) : dg;

    float asrc = a_src[h], adst = a_dst[h], bh = bias[h];

    float sv = HT[h * NN + sg * 512 + t];
    float hd = HT[h * NN + dg * 512 + t];
    float kk = sv * asrc;

    cnt[t] = 0;

    // block min/max of keys
    float mx = kk, mn = kk;
#pragma unroll
    for (int o = 16; o; o >>= 1) {
        mx = fmaxf(mx, __shfl_xor_sync(0xffffffffu, mx, o));
        mn = fminf(mn, __shfl_xor_sync(0xffffffffu, mn, o));
    }
    if (lane == 0) { redM[w] = mx; redm[w] = mn; }
    __syncthreads();  // covers cnt zeroing too
    float M = redM[0], m = redm[0];
#pragma unroll
    for (int i = 1; i < 16; i++) {
        M = fmaxf(M, redM[i]);
        m = fminf(m, redm[i]);
    }
    float range = M - m;
    float scale = (range > 0.f) ? (511.0f / range) : 0.f;

    // P values (exact; shift by M)
    float q1 = __expf(kk - M);
    float q2 = __expf(NSLOPE * (kk - M));
    float4 P4 = make_float4(q1, q1 * sv, q2, q2 * sv);

    // histogram count + slot
    int b = min((int)((kk - m) * scale), 511);
    int slot = atomicAdd(&cnt[b], 1);
    __syncthreads();  // all counts final

    // exclusive int scan over 512 bins -> bstart
    int c0 = cnt[t];
    int incl = c0;
#pragma unroll
    for (int d = 1; d < 32; d <<= 1) {
        int x = __shfl_up_sync(0xffffffffu, incl, d);
        if (lane >= d) incl += x;
    }
    if (lane == 31) wtot[w] = incl;
    __syncthreads();
    int base = 0;
#pragma unroll
    for (int ww = 0; ww < 16; ww++)
        if (ww < w) base += wtot[ww];
    bstart[t] = base + incl - c0;
    if (t == 511) bstart[512] = 512;
    __syncthreads();

    // scatter into bin-sorted order
    int pos = bstart[b] + slot;
    sKsc[pos] = kk;
    sP4[pos] = P4;
    __syncthreads();

    // float4 scans over scattered (key-ordered by bin) positions
    float4 q = sP4[t];
    float2 p1 = make_float2(q.x, q.y);
    float2 p2 = make_float2(q.z, q.w);

    float2 tincl = warp_incl_scan2(p2, lane);   // inclusive prefix of p2
    float2 texcl;
    texcl.x = __shfl_up_sync(0xffffffffu, tincl.x, 1);
    texcl.y = __shfl_up_sync(0xffffffffu, tincl.y, 1);
    if (lane == 0) texcl = make_float2(0.f, 0.f);
    if (lane == 31) wt2[w] = tincl;

    float2 sincl = warp_incl_sufscan2(p1, lane);  // inclusive suffix of p1
    if (lane == 0) wt1[w] = sincl;
    __syncthreads();

    float2 base2 = texcl, base1 = make_float2(0.f, 0.f);
#pragma unroll
    for (int ww = 0; ww < 16; ww++) {
        if (ww < w) { base2.x += wt2[ww].x; base2.y += wt2[ww].y; }
        if (ww > w) { base1.x += wt1[ww].x; base1.y += wt1[ww].y; }
    }
    sSP[t] = make_float4(base1.x + sincl.x, base1.y + sincl.y, base2.x, base2.y);
    if (t == 511)
        sSP[512] = make_float4(0.f, 0.f, base2.x + p2.x, base2.y + p2.y);
    __syncthreads();

    // per-dst: bin lookup + exact boundary resolution
    float adv = hd * adst;
    float thr = -adv;
    float S1, S1v, S2, S2v;
    if (thr < m) {
        float4 Sv = sSP[0];         // suffix incl. 0 = total branch1; prefix 0
        S1 = Sv.x; S1v = Sv.y; S2 = 0.f; S2v = 0.f;
    } else if (thr >= M) {
        float4 Sv = sSP[512];       // suffix 0; prefix = total branch2
        S1 = 0.f; S1v = 0.f; S2 = Sv.z; S2v = Sv.w;
    } else {
        int bt = min((int)((thr - m) * scale), 511);
        int s = bstart[bt], e = bstart[bt + 1];
        float4 A = sSP[e];   // suffix over bins > bt
        float4 Bp = sSP[s];  // prefix over bins < bt
        S1 = A.x; S1v = A.y; S2 = Bp.z; S2v = Bp.w;
        for (int i = s; i < e; i++) {
            float kx = sKsc[i];
            float4 qe = sP4[i];
            if (kx > thr) { S1 += qe.x; S1v += qe.y; }
            else          { S2 += qe.z; S2v += qe.w; }
        }
    }

    float T = M + adv;
    float tmax = T, ts = 0.f;
    if (CROSS) {
        ts = hd * asrc + adv;  // self-loop score
        tmax = fmaxf(tmax, ts);
    }
    float C = lrelu(tmax);
    float f1 = __expf(T - C);
    float f2 = __expf(NSLOPE * T - C);
    float num = f1 * S1v + f2 * S2v;
    float den = f1 * S1 + f2 * S2;
    if (CROSS) {
        float ws = __expf(lrelu(ts) - C);
        num = fmaf(ws, hd, num);
        den += ws;
    }
    float o = num / (den + 1e-16f) + bh;
    o = o > 0.f ? o : expm1f(o);  // ELU
    XTo[h * NN + dg * 512 + t] = o;
}

// ---------------------------------------------------------------------------
__global__ void dots_kernel(const float* __restrict__ H, const float* __restrict__ a_s,
                            const float* __restrict__ a_d, float* __restrict__ asf,
                            float* __restrict__ adf) {
    int n = blockIdx.x * 8 + (threadIdx.x >> 5);
    int lane = threadIdx.x & 31;
    float4 hv = reinterpret_cast<const float4*>(H + n * F)[lane];
    float4 s4 = reinterpret_cast<const float4*>(a_s)[lane];
    float4 d4 = reinterpret_cast<const float4*>(a_d)[lane];
    float s1 = hv.x * s4.x + hv.y * s4.y + hv.z * s4.z + hv.w * s4.w;
    float s2 = hv.x * d4.x + hv.y * d4.y + hv.z * d4.z + hv.w * d4.w;
#pragma unroll
    for (int o = 16; o; o >>= 1) {
        s1 += __shfl_xor_sync(0xffffffffu, s1, o);
        s2 += __shfl_xor_sync(0xffffffffu, s2, o);
    }
    if (lane == 0) { asf[n] = s1; adf[n] = s2; }
}

// final cross-attention: 8 dsts/block, 256 threads (128 cols x 2 s-halves)
__global__ void final_attn(const float* __restrict__ H, const float* __restrict__ asf,
                           const float* __restrict__ adf, const float* __restrict__ bias,
                           float* __restrict__ out) {
    int d0 = blockIdx.x * 8;
    int dg = d0 >> 9;
    int sg = 1 - dg;
    int tid = threadIdx.x;
    int col = tid & 127, sh = tid >> 7;
    int w = tid >> 5, lane = tid & 31;

    __shared__ float sAsf[512];
    __shared__ float4 swq[512][2];
    __shared__ float sAdf[8], sM[8], sSelf[8], sDen[8];
    __shared__ float pr[8][128];
    __shared__ float dred[8][256];
    __shared__ float red[8];

    float mloc = -1e30f;
    for (int s = tid; s < 512; s += 256) {
        float v = asf[sg * 512 + s];
        sAsf[s] = v;
        mloc = fmaxf(mloc, v);
    }
#pragma unroll
    for (int o = 16; o; o >>= 1) mloc = fmaxf(mloc, __shfl_xor_sync(0xffffffffu, mloc, o));
    if (lane == 0) red[w] = mloc;
    __syncthreads();
    float maxasf = red[0];
#pragma unroll
    for (int ww = 1; ww < 8; ww++) maxasf = fmaxf(maxasf, red[ww]);

    if (tid < 8) {
        int dn = d0 + tid;
        float ad = adf[dn];
        float ts = asf[dn] + ad;
        float tmax = fmaxf(maxasf + ad, ts);
        float mm = lrelu(tmax);
        sAdf[tid] = ad;
        sM[tid] = mm;
        sSelf[tid] = __expf(lrelu(ts) - mm);
    }
    __syncthreads();

    float dl[8] = {0, 0, 0, 0, 0, 0, 0, 0};
    for (int s = tid; s < 512; s += 256) {
        float a = sAsf[s];
        float wv[8];
#pragma unroll
        for (int d = 0; d < 8; d++) {
            wv[d] = __expf(lrelu(a + sAdf[d]) - sM[d]);
            dl[d] += wv[d];
        }
        swq[s][0] = make_float4(wv[0], wv[1], wv[2], wv[3]);
        swq[s][1] = make_float4(wv[4], wv[5], wv[6], wv[7]);
    }
#pragma unroll
    for (int d = 0; d < 8; d++) dred[d][tid] = dl[d];
    __syncthreads();
    {
        float x = dred[w][lane] + dred[w][lane + 32] + dred[w][lane + 64] + dred[w][lane + 96] +
                  dred[w][lane + 128] + dred[w][lane + 160] + dred[w][lane + 192] + dred[w][lane + 224];
#pragma unroll
        for (int o = 16; o; o >>= 1) x += __shfl_xor_sync(0xffffffffu, x, o);
        if (lane == 0) sDen[w] = x;
    }
    __syncthreads();

    float acc[8] = {0, 0, 0, 0, 0, 0, 0, 0};
    const float* Hs = H + (sg * 512 + sh * 256) * F + col;
#pragma unroll 2
    for (int s = 0; s < 256; s++) {
        float hv = Hs[s * F];
        int ss = sh * 256 + s;
        float4 w0 = swq[ss][0];
        float4 w1 = swq[ss][1];
        acc[0] = fmaf(w0.x, hv, acc[0]);
        acc[1] = fmaf(w0.y, hv, acc[1]);
        acc[2] = fmaf(w0.z, hv, acc[2]);
        acc[3] = fmaf(w0.w, hv, acc[3]);
        acc[4] = fmaf(w1.x, hv, acc[4]);
        acc[5] = fmaf(w1.y, hv, acc[5]);
        acc[6] = fmaf(w1.z, hv, acc[6]);
        acc[7] = fmaf(w1.w, hv, acc[7]);
    }
    if (sh) {
#pragma unroll
        for (int d = 0; d < 8; d++) pr[d][col] = acc[d];
    }
    __syncthreads();
    if (!sh) {
        float bc = bias[col];
#pragma unroll
        for (int d = 0; d < 8; d++) {
            int dn = d0 + d;
            float Hdv = H[dn * F + col];
            float num = acc[d] + pr[d][col] + sSelf[d] * Hdv;
            out[dn * F + col] = num / (sDen[d] + sSelf[d] + 1e-16f) + bc;
        }
    }
}

// ---------------------------------------------------------------------------
extern "C" void kernel_launch(void* const* d_in, const int* in_sizes, int n_in,
                              void* d_out, int out_size) {
    const float* desc1 = (const float*)d_in[0];
    const float* desc2 = (const float*)d_in[1];
    const float* W1 = (const float*)d_in[2];
    const float* as1 = (const float*)d_in[3];
    const float* ad1 = (const float*)d_in[4];
    const float* b1 = (const float*)d_in[5];
    const float* W2 = (const float*)d_in[6];
    const float* as2 = (const float*)d_in[7];
    const float* ad2 = (const float*)d_in[8];
    const float* b2 = (const float*)d_in[9];
    float* out = (float*)d_out;

    float *XT, *HT, *H, *asf, *adf;
    cudaGetSymbolAddress((void**)&XT, g_XT);
    cudaGetSymbolAddress((void**)&HT, g_HT);
    cudaGetSymbolAddress((void**)&H, g_H);
    cudaGetSymbolAddress((void**)&asf, g_asf);
    cudaGetSymbolAddress((void**)&adf, g_adf);

    dim3 ag(128, 2);
    const float* np = nullptr;
    // conv1: inside (concat fused into gemm)
    gemmW<0><<<128, 512>>>(np, desc1, desc2, W1, HT);
    attnH<false><<<ag, 512>>>(HT, as1, ad1, b1, XT);
    // conv2: cross
    gemmW<1><<<128, 512>>>(XT, np, np, W1, HT);
    attnH<true><<<ag, 512>>>(HT, as1, ad1, b1, XT);
    // conv3: inside
    gemmW<1><<<128, 512>>>(XT, np, np, W1, HT);
    attnH<false><<<ag, 512>>>(HT, as1, ad1, b1, XT);
    // conv4: cross
    gemmW<1><<<128, 512>>>(XT, np, np, W1, HT);
    attnH<true><<<ag, 512>>>(HT, as1, ad1, b1, XT);
    // final conv: cross, heads=1, out_ch=128 (row-major H)
    gemmW<2><<<128, 512>>>(XT, np, np, W2, H);
    dots_kernel<<<128, 256>>>(H, as2, ad2, asf, adf);
    final_attn<<<128, 256>>>(H, asf, adf, b2, out);
}

// round 17
// speedup vs baseline: 1.1139x; 1.0134x over previous
#include <cuda_runtime.h>
#include <math.h>

#define NSLOPE 0.2f
#define NN 1024
#define F 128

__device__ float g_XT[NN * F];   // feature-major activations [f][n]
__device__ float g_HT[NN * F];   // feature-major conv features [f][n]
__device__ float g_H[NN * F];    // row-major (final conv only)
__device__ float g_asf[NN];
__device__ float g_adf[NN];

__device__ __forceinline__ float lrelu(float x) { return x > 0.f ? x : NSLOPE * x; }

// ---------------------------------------------------------------------------
// GEMM v4: grid 128 (8 nodes/block), block 512 = 4 k-groups x 128 cols.
// KEY CHANGE vs R16: the thread's full 32-element W slice is prefetched into
// registers as 32 INDEPENDENT L2 loads (MLP=32, one latency exposure) issued
// in parallel with the x smem staging, instead of 8 serialized MLP=4 rounds.
// Main loop is then pure smem(x)+FMA. k-partials combined via smem in fixed
// order (deterministic).
// MODE 0: read desc1|desc2 rows, write HT.  MODE 1: read XT, write HT.
// MODE 2: read XT, write H (row-major).
template <int MODE>
__global__ void __launch_bounds__(512)
gemmW(const float* __restrict__ XT, const float* __restrict__ d1,
      const float* __restrict__ d2, const float* __restrict__ W,
      float* __restrict__ OUT) {
    __shared__ __align__(16) float xs[8][128];
    __shared__ float pr[3][8][128];  // partials from ks = 1..3
    int tid = threadIdx.x;
    int c = tid & 127;
    int ks = tid >> 7;  // 0..3
    int n0 = blockIdx.x * 8;

    // prefetch W slice (32 independent loads; all in flight at once)
    const float* Wp = W + (ks * 32) * F + c;
    float wreg[32];
#pragma unroll
    for (int i = 0; i < 32; i++) wreg[i] = Wp[i * F];

    // stage the 8 input rows into xs[r][k] (overlaps with W loads)
    if (MODE == 0) {
#pragma unroll
        for (int i = 0; i < 2; i++) {
            int u = tid + i * 512;  // 0..1023
            int r = u >> 7, f = u & 127;
            int n = n0 + r;
            xs[r][f] = (n < 512) ? d1[n * F + f] : d2[(n - 512) * F + f];
        }
    } else {
        if (tid < 256) {
            int k = tid >> 1, q = tid & 1;
            float4 x4 = reinterpret_cast<const float4*>(XT)[k * 256 + (n0 >> 2) + q];
            xs[q * 4 + 0][k] = x4.x;
            xs[q * 4 + 1][k] = x4.y;
            xs[q * 4 + 2][k] = x4.z;
            xs[q * 4 + 3][k] = x4.w;
        }
    }
    __syncthreads();

    float acc[8] = {0, 0, 0, 0, 0, 0, 0, 0};
#pragma unroll
    for (int kq = 0; kq < 8; kq++) {
        int k4 = ks * 32 + kq * 4;
        float w0 = wreg[kq * 4 + 0];
        float w1 = wreg[kq * 4 + 1];
        float w2 = wreg[kq * 4 + 2];
        float w3 = wreg[kq * 4 + 3];
#pragma unroll
        for (int r = 0; r < 8; r++) {
            float4 x = *reinterpret_cast<const float4*>(&xs[r][k4]);
            acc[r] = fmaf(x.x, w0, fmaf(x.y, w1, fmaf(x.z, w2, fmaf(x.w, w3, acc[r]))));
        }
    }

    if (ks) {
#pragma unroll
        for (int r = 0; r < 8; r++) pr[ks - 1][r][c] = acc[r];
    }
    __syncthreads();
    if (!ks) {
        float o[8];
#pragma unroll
        for (int r = 0; r < 8; r++)
            o[r] = acc[r] + pr[0][r][c] + pr[1][r][c] + pr[2][r][c];
        if (MODE == 2) {
#pragma unroll
            for (int r = 0; r < 8; r++) OUT[(n0 + r) * F + c] = o[r];
        } else {
            float* p = OUT + c * NN + n0;
            *reinterpret_cast<float4*>(p) = make_float4(o[0], o[1], o[2], o[3]);
            *reinterpret_cast<float4*>(p + 4) = make_float4(o[4], o[5], o[6], o[7]);
        }
    }
}

// ---------------------------------------------------------------------------
__device__ __forceinline__ float2 warp_incl_scan2(float2 v, int lane) {
#pragma unroll
    for (int d = 1; d < 32; d <<= 1) {
        float x = __shfl_up_sync(0xffffffffu, v.x, d);
        float y = __shfl_up_sync(0xffffffffu, v.y, d);
        if (lane >= d) { v.x += x; v.y += y; }
    }
    return v;
}
__device__ __forceinline__ float2 warp_incl_sufscan2(float2 v, int lane) {
#pragma unroll
    for (int d = 1; d < 32; d <<= 1) {
        float x = __shfl_down_sync(0xffffffffu, v.x, d);
        float y = __shfl_down_sync(0xffffffffu, v.y, d);
        if (lane + d < 32) { v.x += x; v.y += y; }
    }
    return v;
}

// ---------------------------------------------------------------------------
// GAT attention (R16-proven): counting-sort/histogram ranking.
// grid (128, 2), 512 threads, 1 element/thread.
template <bool CROSS>
__global__ void attnH(const float* __restrict__ HT, const float* __restrict__ a_src,
                      const float* __restrict__ a_dst, const float* __restrict__ bias,
                      float* __restrict__ XTo) {
    __shared__ float sKsc[512];                 // scattered keys
    __shared__ __align__(16) float4 sP4[512];   // scattered (P1,P1v,P2,P2v)
    __shared__ __align__(16) float4 sSP[513];   // (suf1,suf1v,pre2,pre2v)
    __shared__ int cnt[512];
    __shared__ int bstart[513];
    __shared__ float redM[16], redm[16];
    __shared__ int wtot[16];
    __shared__ float2 wt1[16], wt2[16];

    int t = threadIdx.x;        // 0..511 = element index
    int lane = t & 31;
    int w = t >> 5;
    int h = blockIdx.x;
    int dg = blockIdx.y;
    int sg = CROSS ? (1 - dg) : dg;

    float asrc = a_src[h], adst = a_dst[h], bh = bias[h];

    float sv = HT[h * NN + sg * 512 + t];
    float hd = HT[h * NN + dg * 512 + t];
    float kk = sv * asrc;

    cnt[t] = 0;

    // block min/max of keys
    float mx = kk, mn = kk;
#pragma unroll
    for (int o = 16; o; o >>= 1) {
        mx = fmaxf(mx, __shfl_xor_sync(0xffffffffu, mx, o));
        mn = fminf(mn, __shfl_xor_sync(0xffffffffu, mn, o));
    }
    if (lane == 0) { redM[w] = mx; redm[w] = mn; }
    __syncthreads();  // covers cnt zeroing too
    float M = redM[0], m = redm[0];
#pragma unroll
    for (int i = 1; i < 16; i++) {
        M = fmaxf(M, redM[i]);
        m = fminf(m, redm[i]);
    }
    float range = M - m;
    float scale = (range > 0.f) ? (511.0f / range) : 0.f;

    // P values (exact; shift by M)
    float q1 = __expf(kk - M);
    float q2 = __expf(NSLOPE * (kk - M));
    float4 P4 = make_float4(q1, q1 * sv, q2, q2 * sv);

    // histogram count + slot
    int b = min((int)((kk - m) * scale), 511);
    int slot = atomicAdd(&cnt[b], 1);
    __syncthreads();  // all counts final

    // exclusive int scan over 512 bins -> bstart
    int c0 = cnt[t];
    int incl = c0;
#pragma unroll
    for (int d = 1; d < 32; d <<= 1) {
        int x = __shfl_up_sync(0xffffffffu, incl, d);
        if (lane >= d) incl += x;
    }
    if (lane == 31) wtot[w] = incl;
    __syncthreads();
    int base = 0;
#pragma unroll
    for (int ww = 0; ww < 16; ww++)
        if (ww < w) base += wtot[ww];
    bstart[t] = base + incl - c0;
    if (t == 511) bstart[512] = 512;
    __syncthreads();

    // scatter into bin-sorted order
    int pos = bstart[b] + slot;
    sKsc[pos] = kk;
    sP4[pos] = P4;
    __syncthreads();

    // float4 scans over scattered (key-ordered by bin) positions
    float4 q = sP4[t];
    float2 p1 = make_float2(q.x, q.y);
    float2 p2 = make_float2(q.z, q.w);

    float2 tincl = warp_incl_scan2(p2, lane);   // inclusive prefix of p2
    float2 texcl;
    texcl.x = __shfl_up_sync(0xffffffffu, tincl.x, 1);
    texcl.y = __shfl_up_sync(0xffffffffu, tincl.y, 1);
    if (lane == 0) texcl = make_float2(0.f, 0.f);
    if (lane == 31) wt2[w] = tincl;

    float2 sincl = warp_incl_sufscan2(p1, lane);  // inclusive suffix of p1
    if (lane == 0) wt1[w] = sincl;
    __syncthreads();

    float2 base2 = texcl, base1 = make_float2(0.f, 0.f);
#pragma unroll
    for (int ww = 0; ww < 16; ww++) {
        if (ww < w) { base2.x += wt2[ww].x; base2.y += wt2[ww].y; }
        if (ww > w) { base1.x += wt1[ww].x; base1.y += wt1[ww].y; }
    }
    sSP[t] = make_float4(base1.x + sincl.x, base1.y + sincl.y, base2.x, base2.y);
    if (t == 511)
        sSP[512] = make_float4(0.f, 0.f, base2.x + p2.x, base2.y + p2.y);
    __syncthreads();

    // per-dst: bin lookup + exact boundary resolution
    float adv = hd * adst;
    float thr = -adv;
    float S1, S1v, S2, S2v;
    if (thr < m) {
        float4 Sv = sSP[0];
        S1 = Sv.x; S1v = Sv.y; S2 = 0.f; S2v = 0.f;
    } else if (thr >= M) {
        float4 Sv = sSP[512];
        S1 = 0.f; S1v = 0.f; S2 = Sv.z; S2v = Sv.w;
    } else {
        int bt = min((int)((thr - m) * scale), 511);
        int s = bstart[bt], e = bstart[bt + 1];
        float4 A = sSP[e];   // suffix over bins > bt
        float4 Bp = sSP[s];  // prefix over bins < bt
        S1 = A.x; S1v = A.y; S2 = Bp.z; S2v = Bp.w;
        for (int i = s; i < e; i++) {
            float kx = sKsc[i];
            float4 qe = sP4[i];
            if (kx > thr) { S1 += qe.x; S1v += qe.y; }
            else          { S2 += qe.z; S2v += qe.w; }
        }
    }

    float T = M + adv;
    float tmax = T, ts = 0.f;
    if (CROSS) {
        ts = hd * asrc + adv;  // self-loop score
        tmax = fmaxf(tmax, ts);
    }
    float C = lrelu(tmax);
    float f1 = __expf(T - C);
    float f2 = __expf(NSLOPE * T - C);
    float num = f1 * S1v + f2 * S2v;
    float den = f1 * S1 + f2 * S2;
    if (CROSS) {
        float ws = __expf(lrelu(ts) - C);
        num = fmaf(ws, hd, num);
        den += ws;
    }
    float o = num / (den + 1e-16f) + bh;
    o = o > 0.f ? o : expm1f(o);  // ELU
    XTo[h * NN + dg * 512 + t] = o;
}

// ---------------------------------------------------------------------------
__global__ void dots_kernel(const float* __restrict__ H, const float* __restrict__ a_s,
                            const float* __restrict__ a_d, float* __restrict__ asf,
                            float* __restrict__ adf) {
    int n = blockIdx.x * 8 + (threadIdx.x >> 5);
    int lane = threadIdx.x & 31;
    float4 hv = reinterpret_cast<const float4*>(H + n * F)[lane];
    float4 s4 = reinterpret_cast<const float4*>(a_s)[lane];
    float4 d4 = reinterpret_cast<const float4*>(a_d)[lane];
    float s1 = hv.x * s4.x + hv.y * s4.y + hv.z * s4.z + hv.w * s4.w;
    float s2 = hv.x * d4.x + hv.y * d4.y + hv.z * d4.z + hv.w * d4.w;
#pragma unroll
    for (int o = 16; o; o >>= 1) {
        s1 += __shfl_xor_sync(0xffffffffu, s1, o);
        s2 += __shfl_xor_sync(0xffffffffu, s2, o);
    }
    if (lane == 0) { asf[n] = s1; adf[n] = s2; }
}

// final cross-attention: 8 dsts/block, 256 threads (128 cols x 2 s-halves)
__global__ void final_attn(const float* __restrict__ H, const float* __restrict__ asf,
                           const float* __restrict__ adf, const float* __restrict__ bias,
                           float* __restrict__ out) {
    int d0 = blockIdx.x * 8;
    int dg = d0 >> 9;
    int sg = 1 - dg;
    int tid = threadIdx.x;
    int col = tid & 127, sh = tid >> 7;
    int w = tid >> 5, lane = tid & 31;

    __shared__ float sAsf[512];
    __shared__ float4 swq[512][2];
    __shared__ float sAdf[8], sM[8], sSelf[8], sDen[8];
    __shared__ float pr[8][128];
    __shared__ float dred[8][256];
    __shared__ float red[8];

    float mloc = -1e30f;
    for (int s = tid; s < 512; s += 256) {
        float v = asf[sg * 512 + s];
        sAsf[s] = v;
        mloc = fmaxf(mloc, v);
    }
#pragma unroll
    for (int o = 16; o; o >>= 1) mloc = fmaxf(mloc, __shfl_xor_sync(0xffffffffu, mloc, o));
    if (lane == 0) red[w] = mloc;
    __syncthreads();
    float maxasf = red[0];
#pragma unroll
    for (int ww = 1; ww < 8; ww++) maxasf = fmaxf(maxasf, red[ww]);

    if (tid < 8) {
        int dn = d0 + tid;
        float ad = adf[dn];
        float ts = asf[dn] + ad;
        float tmax = fmaxf(maxasf + ad, ts);
        float mm = lrelu(tmax);
        sAdf[tid] = ad;
        sM[tid] = mm;
        sSelf[tid] = __expf(lrelu(ts) - mm);
    }
    __syncthreads();

    float dl[8] = {0, 0, 0, 0, 0, 0, 0, 0};
    for (int s = tid; s < 512; s += 256) {
        float a = sAsf[s];
        float wv[8];
#pragma unroll
        for (int d = 0; d < 8; d++) {
            wv[d] = __expf(lrelu(a + sAdf[d]) - sM[d]);
            dl[d] += wv[d];
        }
        swq[s][0] = make_float4(wv[0], wv[1], wv[2], wv[3]);
        swq[s][1] = make_float4(wv[4], wv[5], wv[6], wv[7]);
    }
#pragma unroll
    for (int d = 0; d < 8; d++) dred[d][tid] = dl[d];
    __syncthreads();
    {
        float x = dred[w][lane] + dred[w][lane + 32] + dred[w][lane + 64] + dred[w][lane + 96] +
                  dred[w][lane + 128] + dred[w][lane + 160] + dred[w][lane + 192] + dred[w][lane + 224];
#pragma unroll
        for (int o = 16; o; o >>= 1) x += __shfl_xor_sync(0xffffffffu, x, o);
        if (lane == 0) sDen[w] = x;
    }
    __syncthreads();

    float acc[8] = {0, 0, 0, 0, 0, 0, 0, 0};
    const float* Hs = H + (sg * 512 + sh * 256) * F + col;
#pragma unroll 2
    for (int s = 0; s < 256; s++) {
        float hv = Hs[s * F];
        int ss = sh * 256 + s;
        float4 w0 = swq[ss][0];
        float4 w1 = swq[ss][1];
        acc[0] = fmaf(w0.x, hv, acc[0]);
        acc[1] = fmaf(w0.y, hv, acc[1]);
        acc[2] = fmaf(w0.z, hv, acc[2]);
        acc[3] = fmaf(w0.w, hv, acc[3]);
        acc[4] = fmaf(w1.x, hv, acc[4]);
        acc[5] = fmaf(w1.y, hv, acc[5]);
        acc[6] = fmaf(w1.z, hv, acc[6]);
        acc[7] = fmaf(w1.w, hv, acc[7]);
    }
    if (sh) {
#pragma unroll
        for (int d = 0; d < 8; d++) pr[d][col] = acc[d];
    }
    __syncthreads();
    if (!sh) {
        float bc = bias[col];
#pragma unroll
        for (int d = 0; d < 8; d++) {
            int dn = d0 + d;
            float Hdv = H[dn * F + col];
            float num = acc[d] + pr[d][col] + sSelf[d] * Hdv;
            out[dn * F + col] = num / (sDen[d] + sSelf[d] + 1e-16f) + bc;
        }
    }
}

// ---------------------------------------------------------------------------
extern "C" void kernel_launch(void* const* d_in, const int* in_sizes, int n_in,
                              void* d_out, int out_size) {
    const float* desc1 = (const float*)d_in[0];
    const float* desc2 = (const float*)d_in[1];
    const float* W1 = (const float*)d_in[2];
    const float* as1 = (const float*)d_in[3];
    const float* ad1 = (const float*)d_in[4];
    const float* b1 = (const float*)d_in[5];
    const float* W2 = (const float*)d_in[6];
    const float* as2 = (const float*)d_in[7];
    const float* ad2 = (const float*)d_in[8];
    const float* b2 = (const float*)d_in[9];
    float* out = (float*)d_out;

    float *XT, *HT, *H, *asf, *adf;
    cudaGetSymbolAddress((void**)&XT, g_XT);
    cudaGetSymbolAddress((void**)&HT, g_HT);
    cudaGetSymbolAddress((void**)&H, g_H);
    cudaGetSymbolAddress((void**)&asf, g_asf);
    cudaGetSymbolAddress((void**)&adf, g_adf);

    dim3 ag(128, 2);
    const float* np = nullptr;
    // conv1: inside (concat fused into gemm)
    gemmW<0><<<128, 512>>>(np, desc1, desc2, W1, HT);
    attnH<false><<<ag, 512>>>(HT, as1, ad1, b1, XT);
    // conv2: cross
    gemmW<1><<<128, 512>>>(XT, np, np, W1, HT);
    attnH<true><<<ag, 512>>>(HT, as1, ad1, b1, XT);
    // conv3: inside
    gemmW<1><<<128, 512>>>(XT, np, np, W1, HT);
    attnH<false><<<ag, 512>>>(HT, as1, ad1, b1, XT);
    // conv4: cross
    gemmW<1><<<128, 512>>>(XT, np, np, W1, HT);
    attnH<true><<<ag, 512>>>(HT, as1, ad1, b1, XT);
    // final conv: cross, heads=1, out_ch=128 (row-major H)
    gemmW<2><<<128, 512>>>(XT, np, np, W2, H);
    dots_kernel<<<128, 256>>>(H, as2, ad2, asf, adf);
    final_attn<<<128, 256>>>(H, asf, adf, b2, out);
}